// round 8
// baseline (speedup 1.0000x reference)
#include <cuda_runtime.h>
#include <math.h>

#define LMAX 20
#define NM   21           // number of m columns (0..20)
#define KVAL 441          // (LMAX+1)^2
#define RANK_ 256
#define BPTS 16           // points per CTA
#define NPV  (BPTS * 2)   // 32 (point,vector) pairs
#define NTHREADS 256
#define PV_STRIDE 65      // padded (coprime with 32 banks)

// --------------------------------------------------------------------------
// Tables (double-precision normd(), product form — same values as the
// passing kernels). float2-packed (A,B).
//   Q(m,m)   = g_seed[m] * pmm
//   Q(m+1,m) = g_c1[m] * ct * Q(m,m)
//   Q(l,m)   = A(l,m) * ct * Q(l-1,m) - B(l,m) * Q(l-2,m)
// g_pi/g_pj/g_pr: bank-aware permutation of the 256 rank pairs into 8
// warp-groups (correct for ANY permutation; only shapes smem conflicts).
// --------------------------------------------------------------------------
__device__ float2 g_AB[NM * NM];
__device__ float  g_seed[NM];
__device__ float  g_c1[NM];
__device__ int    g_pi[RANK_];
__device__ int    g_pj[RANK_];
__device__ int    g_pr[RANK_];

__device__ __forceinline__ double normd(int l, int m) {
    // sqrt( (2l+1)/(4pi) * (l-m)!/(l+m)! ) -- product then one divide
    double p = 1.0;
    for (int k = l - m + 1; k <= l + m; ++k) p *= (double)k;  // (l+m)!/(l-m)!
    return sqrt((2.0 * l + 1.0) / (4.0 * 3.14159265358979323846) / p);
}

__global__ void init_tables_kernel(const int* __restrict__ ri,
                                   const int* __restrict__ rj) {
    __shared__ int s_i[RANK_];
    __shared__ int s_j[RANK_];
    int i = threadIdx.x;

    // Parallel coalesced staging of rank indices (for the serial greedy).
    if (i < RANK_) { s_i[i] = ri[i]; s_j[i] = rj[i]; }

    if (i < NM) {
        int m = i;
        double s = normd(m, m);
        if (m > 0) s *= 1.4142135623730951;   // sqrt(2) for m != 0 terms
        g_seed[m] = (float)s;
        g_c1[m] = (m < LMAX)
            ? (float)((2.0 * m + 1.0) * normd(m + 1, m) / normd(m, m))
            : 0.f;
    }
    for (int idx = i; idx < NM * NM; idx += blockDim.x) {
        int l = idx / NM, m = idx % NM;
        float2 ab = make_float2(0.f, 0.f);
        if (l >= m + 2) {
            ab.x = (float)((2.0 * l - 1.0) / (double)(l - m)
                           * normd(l, m) / normd(l - 1, m));
            ab.y = (float)((double)(l + m - 1) / (double)(l - m)
                           * normd(l, m) / normd(l - 2, m));
        }
        g_AB[idx] = ab;
    }
    __syncthreads();

    // Greedy bank-aware grouping, now fed from SMEM (fast) instead of
    // serial global loads. Identical output permutation to round 7.
    if (i == 0) {
        unsigned cap[8] = {0, 0, 0, 0, 0, 0, 0, 0};
        unsigned mi[8]  = {0, 0, 0, 0, 0, 0, 0, 0};
        unsigned mj[8]  = {0, 0, 0, 0, 0, 0, 0, 0};
        for (int r = 0; r < RANK_; ++r) {
            int ii = s_i[r], jj = s_j[r];
            unsigned bi = 1u << (ii & 31);
            unsigned bj = 1u << (jj & 31);
            int best = -1;
            for (int g = 0; g < 8 && best < 0; ++g)       // both banks free
                if (cap[g] < 32 && !(mi[g] & bi) && !(mj[g] & bj)) best = g;
            for (int g = 0; g < 8 && best < 0; ++g)       // i-bank free
                if (cap[g] < 32 && !(mi[g] & bi)) best = g;
            for (int g = 0; g < 8 && best < 0; ++g)       // j-bank free
                if (cap[g] < 32 && !(mj[g] & bj)) best = g;
            for (int g = 0; g < 8 && best < 0; ++g)       // any space
                if (cap[g] < 32) best = g;
            int slot = best * 32 + (int)cap[best];
            cap[best]++; mi[best] |= bi; mj[best] |= bj;
            g_pi[slot] = ii; g_pj[slot] = jj; g_pr[slot] = r;
        }
    }
}

// --------------------------------------------------------------------------
// Main kernel: one CTA = BPTS points = 32 (point,vector) pairs.
// Phase 0: warp 0, lane = pv: ct + trig/diagonal chains into s_pv.
// Phase 1: lane = pv; warp w handles m in {w, 15-w, 16+w(w<5)} (balanced).
// Phase 2: thread t owns permuted rank slot t for all points.
// --------------------------------------------------------------------------
__global__ __launch_bounds__(NTHREADS, 1) void sh_kernel(
    const float* __restrict__ coords, float* __restrict__ out, int npts)
{
    extern __shared__ float smem[];
    float*  s_psi  = smem;                               // NPV*KVAL
    float*  s_pv   = s_psi + NPV * KVAL;                 // NPV*PV_STRIDE
    float2* s_AB   = (float2*)(s_pv + NPV * PV_STRIDE);  // 441 float2
    float*  s_seed = (float*)(s_AB + NM * NM);           // 21
    float*  s_c1   = s_seed + NM;                        // 21

    const int t    = threadIdx.x;
    const int warp = t >> 5;
    const int lane = t & 31;
    const int p0   = blockIdx.x * BPTS;

    // Per-thread permuted rank data for phase 2.
    const int pi = g_pi[t];
    const int pj = g_pj[t];
    const int pr = g_pr[t];

    // Stage tables.
    for (int idx = t; idx < NM * NM; idx += NTHREADS) s_AB[idx] = g_AB[idx];
    if (t < NM) { s_seed[t] = g_seed[t]; s_c1[t] = g_c1[t]; }

    // Phase 0: per (point, vector) trig / diagonal chains (32 threads).
    if (t < NPV) {
        int p = t >> 1, v = t & 1;
        float ct = 0.f, st = 0.f, ca = 1.f, sa = 0.f;
        if (p0 + p < npts) {
            const float* cp = coords + (size_t)(p0 + p) * 6 + v * 3;
            float X = cp[0], Yc = cp[1], Z = cp[2];
            float r = sqrtf(X * X + Yc * Yc + Z * Z);
            ct = Z / r;
            ct = fminf(1.f, fmaxf(-1.f, ct));
            st = sqrtf(fmaxf(0.f, 1.f - ct * ct));     // sin(arccos(ct)) >= 0
            float rxy2 = X * X + Yc * Yc;
            if (rxy2 > 0.f) {                          // atan2(0,0)=0
                float irxy = rsqrtf(rxy2);
                ca = X * irxy; sa = Yc * irxy;
            }
        }
        float* pvd = s_pv + t * PV_STRIDE;
        pvd[0] = ct;
        float cm = 1.f, sv = 0.f, pm = 1.f;
        pvd[1] = cm; pvd[22] = sv; pvd[43] = pm;
        #pragma unroll
        for (int m = 1; m <= LMAX; ++m) {
            float cn = cm * ca - sv * sa;              // cos(m*azim)
            sv = cm * sa + sv * ca;                    // sin(m*azim)
            cm = cn;
            pm *= (1.f - 2.f * (float)m) * st;         // Condon-Shortley diag
            pvd[1 + m] = cm; pvd[22 + m] = sv; pvd[43 + m] = pm;
        }
    }
    __syncthreads();

    // Phase 1: lane = pv, warp-uniform balanced m list.
    if (p0 + (lane >> 1) < npts) {
        int mvals[3];
        mvals[0] = warp;                 // rows 21..14
        mvals[1] = 15 - warp;            // rows  6..13
        mvals[2] = 16 + warp;            // rows  5..1 (warps 0..4 only)
        const int nmv = (warp < 5) ? 3 : 2;

        const float* pvd = s_pv + lane * PV_STRIDE;
        const float  ct  = pvd[0];
        float* ps = s_psi + lane * KVAL;

        for (int k = 0; k < nmv; ++k) {
            const int m = mvals[k];
            float cm = pvd[1 + m], sv = pvd[22 + m], pm = pvd[43 + m];
            float q2 = s_seed[m] * pm;                 // l = m
            int base = m * (m + 1);
            if (m) ps[base - m] = q2 * sv;             // warp-uniform branch
            ps[base + m] = q2 * cm;
            if (m < LMAX) {
                float q1 = s_c1[m] * ct * q2;          // l = m+1
                base = (m + 1) * (m + 2);
                if (m) ps[base - m] = q1 * sv;
                ps[base + m] = q1 * cm;
                for (int l = m + 2; l <= LMAX; ++l) {
                    float2 ab = s_AB[l * NM + m];      // one LDS.64 broadcast
                    float qn = ab.x * ct * q1 - ab.y * q2;
                    q2 = q1; q1 = qn;
                    base += 2 * l;                     // = l*(l+1)
                    if (m) ps[base - m] = qn * sv;
                    ps[base + m] = qn * cm;
                }
            }
        }
    }
    __syncthreads();

    // Phase 2: permuted gathered products, minimal address ALU.
    if (p0 + BPTS <= npts) {
        float* o = out + (size_t)p0 * RANK_ + pr;
        const float* pa = s_psi + pi;
        const float* pb = s_psi + KVAL + pj;
        #pragma unroll
        for (int p = 0; p < BPTS; ++p)
            o[p * RANK_] = pa[p * 2 * KVAL] * pb[p * 2 * KVAL];
    } else {
        for (int p = 0; p < BPTS; ++p) {
            int gp = p0 + p;
            if (gp < npts)
                out[(size_t)gp * RANK_ + pr] =
                    s_psi[(2 * p) * KVAL + pi] * s_psi[(2 * p + 1) * KVAL + pj];
        }
    }
}

extern "C" void kernel_launch(void* const* d_in, const int* in_sizes, int n_in,
                              void* d_out, int out_size) {
    const float* coords = (const float*)d_in[0];
    const int*   ri     = (const int*)d_in[1];
    const int*   rj     = (const int*)d_in[2];
    float*       out    = (float*)d_out;
    int npts = in_sizes[0] / 6;

    const size_t SMEM = (size_t)(NPV * KVAL            // psi
                                 + NPV * PV_STRIDE     // chains
                                 + 2 * NM * NM         // AB (float2)
                                 + 2 * NM)             // seed, c1
                        * sizeof(float);
    cudaFuncSetAttribute((const void*)sh_kernel,
                         cudaFuncAttributeMaxDynamicSharedMemorySize, (int)SMEM);

    init_tables_kernel<<<1, 512>>>(ri, rj);
    int grid = (npts + BPTS - 1) / BPTS;
    sh_kernel<<<grid, NTHREADS, SMEM>>>(coords, out, npts);
}

// round 9
// speedup vs baseline: 1.9628x; 1.9628x over previous
#include <cuda_runtime.h>
#include <math.h>

#define LMAX 20
#define NM   21           // number of m columns (0..20)
#define KVAL 441          // (LMAX+1)^2
#define RANK_ 256
#define BPTS 16           // points per CTA
#define NPV  (BPTS * 2)   // 32 (point,vector) pairs
#define NTHREADS 512      // 16 warps: one m-column per warp
#define PV_STRIDE 65      // padded (coprime with 32 banks)

// --------------------------------------------------------------------------
// Tables (double-precision normd(), product form — identical values to all
// passing kernels). float2-packed (A,B). NO rank permutation (the greedy was
// ~100us of serial init time with unproven benefit).
//   Q(m,m)   = g_seed[m] * pmm
//   Q(m+1,m) = g_c1[m] * ct * Q(m,m)
//   Q(l,m)   = A(l,m) * ct * Q(l-1,m) - B(l,m) * Q(l-2,m)
// --------------------------------------------------------------------------
__device__ float2 g_AB[NM * NM];
__device__ float  g_seed[NM];
__device__ float  g_c1[NM];

__device__ __forceinline__ double normd(int l, int m) {
    // sqrt( (2l+1)/(4pi) * (l-m)!/(l+m)! ) -- product then one divide
    double p = 1.0;
    for (int k = l - m + 1; k <= l + m; ++k) p *= (double)k;  // (l+m)!/(l-m)!
    return sqrt((2.0 * l + 1.0) / (4.0 * 3.14159265358979323846) / p);
}

__global__ void init_tables_kernel() {
    int i = threadIdx.x;
    if (i < NM) {
        int m = i;
        double s = normd(m, m);
        if (m > 0) s *= 1.4142135623730951;   // sqrt(2) for m != 0 terms
        g_seed[m] = (float)s;
        g_c1[m] = (m < LMAX)
            ? (float)((2.0 * m + 1.0) * normd(m + 1, m) / normd(m, m))
            : 0.f;
    }
    for (int idx = i; idx < NM * NM; idx += blockDim.x) {
        int l = idx / NM, m = idx % NM;
        float2 ab = make_float2(0.f, 0.f);
        if (l >= m + 2) {
            ab.x = (float)((2.0 * l - 1.0) / (double)(l - m)
                           * normd(l, m) / normd(l - 1, m));
            ab.y = (float)((double)(l + m - 1) / (double)(l - m)
                           * normd(l, m) / normd(l - 2, m));
        }
        g_AB[idx] = ab;
    }
}

// --------------------------------------------------------------------------
// Main kernel: one CTA = BPTS points = 32 (point,vector) pairs, 16 warps.
// Phase 0: warp 0, lane = pv: ct + trig/diagonal chains into s_pv.
// Phase 1: lane = pv; warp w handles m = w, plus m = 27-w for w in 7..11.
//          Critical path = 21 rows (minimum possible, the m=0 column).
// Phase 2: thread t owns rank (t & 255) for points (t>>8), (t>>8)+2, ...
//          Rolled loop (round-7 form) — NOT batch-unrolled (round-8 lesson).
// --------------------------------------------------------------------------
__global__ __launch_bounds__(NTHREADS, 1) void sh_kernel(
    const float* __restrict__ coords, const int* __restrict__ ri,
    const int* __restrict__ rj, float* __restrict__ out, int npts)
{
    extern __shared__ float smem[];
    float*  s_psi  = smem;                               // NPV*KVAL
    float*  s_pv   = s_psi + NPV * KVAL;                 // NPV*PV_STRIDE
    float2* s_AB   = (float2*)(s_pv + NPV * PV_STRIDE);  // 441 float2
    float*  s_seed = (float*)(s_AB + NM * NM);           // 21
    float*  s_c1   = s_seed + NM;                        // 21

    const int t    = threadIdx.x;
    const int warp = t >> 5;
    const int lane = t & 31;
    const int p0   = blockIdx.x * BPTS;

    // Per-thread rank data for phase 2 (identity mapping, coalesced LDG).
    const int rk = t & (RANK_ - 1);
    const int pi = ri[rk];
    const int pj = rj[rk];

    // Stage tables.
    for (int idx = t; idx < NM * NM; idx += NTHREADS) s_AB[idx] = g_AB[idx];
    if (t < NM) { s_seed[t] = g_seed[t]; s_c1[t] = g_c1[t]; }

    // Phase 0: per (point, vector) trig / diagonal chains (32 threads).
    if (t < NPV) {
        int p = t >> 1, v = t & 1;
        float ct = 0.f, st = 0.f, ca = 1.f, sa = 0.f;
        if (p0 + p < npts) {
            const float* cp = coords + (size_t)(p0 + p) * 6 + v * 3;
            float X = cp[0], Yc = cp[1], Z = cp[2];
            float r = sqrtf(X * X + Yc * Yc + Z * Z);
            ct = Z / r;
            ct = fminf(1.f, fmaxf(-1.f, ct));
            st = sqrtf(fmaxf(0.f, 1.f - ct * ct));     // sin(arccos(ct)) >= 0
            float rxy2 = X * X + Yc * Yc;
            if (rxy2 > 0.f) {                          // atan2(0,0)=0
                float irxy = rsqrtf(rxy2);
                ca = X * irxy; sa = Yc * irxy;
            }
        }
        float* pvd = s_pv + t * PV_STRIDE;
        pvd[0] = ct;
        float cm = 1.f, sv = 0.f, pm = 1.f;
        pvd[1] = cm; pvd[22] = sv; pvd[43] = pm;
        #pragma unroll
        for (int m = 1; m <= LMAX; ++m) {
            float cn = cm * ca - sv * sa;              // cos(m*azim)
            sv = cm * sa + sv * ca;                    // sin(m*azim)
            cm = cn;
            pm *= (1.f - 2.f * (float)m) * st;         // Condon-Shortley diag
            pvd[1 + m] = cm; pvd[22 + m] = sv; pvd[43 + m] = pm;
        }
    }
    __syncthreads();

    // Phase 1: lane = pv; warp-uniform m columns (critical path 21 rows).
    if (p0 + (lane >> 1) < npts) {
        const float* pvd = s_pv + lane * PV_STRIDE;
        const float  ct  = pvd[0];
        float* ps = s_psi + lane * KVAL;

        int mvals[2];
        mvals[0] = warp;                                     // m = 0..15
        mvals[1] = (warp >= 7 && warp <= 11) ? 27 - warp : -1;  // m = 20..16
        const int nmv = (mvals[1] >= 0) ? 2 : 1;

        for (int k = 0; k < nmv; ++k) {
            const int m = mvals[k];
            float cm = pvd[1 + m], sv = pvd[22 + m], pm = pvd[43 + m];
            float q2 = s_seed[m] * pm;                 // l = m
            int base = m * (m + 1);
            if (m) ps[base - m] = q2 * sv;             // warp-uniform branch
            ps[base + m] = q2 * cm;
            if (m < LMAX) {
                float q1 = s_c1[m] * ct * q2;          // l = m+1
                base = (m + 1) * (m + 2);
                if (m) ps[base - m] = q1 * sv;
                ps[base + m] = q1 * cm;
                for (int l = m + 2; l <= LMAX; ++l) {
                    float2 ab = s_AB[l * NM + m];      // one LDS.64 broadcast
                    float qn = ab.x * ct * q1 - ab.y * q2;
                    q2 = q1; q1 = qn;
                    base += 2 * l;                     // = l*(l+1)
                    if (m) ps[base - m] = qn * sv;
                    ps[base + m] = qn * cm;
                }
            }
        }
    }
    __syncthreads();

    // Phase 2: rolled loop, two points per thread, coalesced stores.
    for (int p = (t >> 8); p < BPTS; p += 2) {
        int gp = p0 + p;
        if (gp < npts) {
            float a = s_psi[(2 * p)     * KVAL + pi];
            float b = s_psi[(2 * p + 1) * KVAL + pj];
            out[(size_t)gp * RANK_ + rk] = a * b;
        }
    }
}

extern "C" void kernel_launch(void* const* d_in, const int* in_sizes, int n_in,
                              void* d_out, int out_size) {
    const float* coords = (const float*)d_in[0];
    const int*   ri     = (const int*)d_in[1];
    const int*   rj     = (const int*)d_in[2];
    float*       out    = (float*)d_out;
    int npts = in_sizes[0] / 6;

    const size_t SMEM = (size_t)(NPV * KVAL            // psi
                                 + NPV * PV_STRIDE     // chains
                                 + 2 * NM * NM         // AB (float2)
                                 + 2 * NM)             // seed, c1
                        * sizeof(float);
    cudaFuncSetAttribute((const void*)sh_kernel,
                         cudaFuncAttributeMaxDynamicSharedMemorySize, (int)SMEM);

    init_tables_kernel<<<1, 512>>>();
    int grid = (npts + BPTS - 1) / BPTS;
    sh_kernel<<<grid, NTHREADS, SMEM>>>(coords, ri, rj, out, npts);
}

// round 10
// speedup vs baseline: 2.5175x; 1.2826x over previous
#include <cuda_runtime.h>
#include <math.h>

#define LMAX 20
#define NM   21           // number of m columns (0..20)
#define KVAL 441          // (LMAX+1)^2
#define RANK_ 256
#define BPTS 16           // points per CTA
#define NPV  (BPTS * 2)   // 32 (point,vector) pairs
#define NTHREADS 512      // 16 warps: one m-column per warp
#define PV_STRIDE 65      // padded (coprime with 32 banks)

// --------------------------------------------------------------------------
// Compile-time tables (same product-form normd() math as all passing rounds,
// evaluated in constexpr double with a Newton sqrt). Stored in __constant__:
// warp-uniform reads go through the constant port (no L1tex traffic), and
// the init kernel + its launch overhead disappear entirely.
//   Q(m,m)   = seed[m] * pmm
//   Q(m+1,m) = c1[m] * ct * Q(m,m)
//   Q(l,m)   = A(l,m) * ct * Q(l-1,m) - B(l,m) * Q(l-2,m)
// --------------------------------------------------------------------------
struct F2 { float x, y; };
struct Tab {
    F2    AB[NM * NM];
    float seed[NM];
    float c1[NM];
};

constexpr double csqrt(double v) {
    double g = v > 1.0 ? v : 1.0;
    for (int i = 0; i < 100; ++i) g = 0.5 * (g + v / g);
    return g;
}

constexpr double cnormd(int l, int m) {
    // sqrt( (2l+1)/(4pi) * (l-m)!/(l+m)! ) -- product then one divide
    double p = 1.0;
    for (int k = l - m + 1; k <= l + m; ++k) p *= (double)k;  // (l+m)!/(l-m)!
    return csqrt((2.0 * l + 1.0) / (4.0 * 3.14159265358979323846) / p);
}

constexpr Tab make_tab() {
    Tab t{};
    for (int m = 0; m <= LMAX; ++m) {
        double s = cnormd(m, m);
        if (m > 0) s *= 1.4142135623730951;   // sqrt(2) for m != 0 terms
        t.seed[m] = (float)s;
        t.c1[m] = (m < LMAX)
            ? (float)((2.0 * m + 1.0) * cnormd(m + 1, m) / cnormd(m, m))
            : 0.f;
    }
    for (int l = 0; l <= LMAX; ++l)
        for (int m = 0; m <= LMAX; ++m) {
            F2 ab{0.f, 0.f};
            if (l >= m + 2) {
                ab.x = (float)((2.0 * l - 1.0) / (double)(l - m)
                               * cnormd(l, m) / cnormd(l - 1, m));
                ab.y = (float)((double)(l + m - 1) / (double)(l - m)
                               * cnormd(l, m) / cnormd(l - 2, m));
            }
            t.AB[l * NM + m] = ab;
        }
    return t;
}

__constant__ Tab c_tab = make_tab();

// --------------------------------------------------------------------------
// Main kernel: one CTA = BPTS points = 32 (point,vector) pairs, 16 warps.
// Phase 0: warp 0, lane = pv: ct + trig/diagonal chains into s_pv.
// Phase 1: lane = pv; warp w handles m = w, plus m = 27-w for w in 7..11.
//          Critical path = 21 rows (minimum possible, the m=0 column).
//          Table reads are warp-uniform __constant__ loads (no smem).
// Phase 2: thread t owns rank (t & 255); rolled loop (round-8 lesson:
//          do NOT batch-unroll the gathers).
// --------------------------------------------------------------------------
__global__ __launch_bounds__(NTHREADS, 1) void sh_kernel(
    const float* __restrict__ coords, const int* __restrict__ ri,
    const int* __restrict__ rj, float* __restrict__ out, int npts)
{
    extern __shared__ float smem[];
    float* s_psi = smem;                    // NPV*KVAL
    float* s_pv  = s_psi + NPV * KVAL;      // NPV*PV_STRIDE

    const int t    = threadIdx.x;
    const int warp = t >> 5;
    const int lane = t & 31;
    const int p0   = blockIdx.x * BPTS;

    // Per-thread rank data for phase 2 (identity mapping, coalesced LDG).
    const int rk = t & (RANK_ - 1);
    const int pi = ri[rk];
    const int pj = rj[rk];

    // Phase 0: per (point, vector) trig / diagonal chains (32 threads).
    if (t < NPV) {
        int p = t >> 1, v = t & 1;
        float ct = 0.f, st = 0.f, ca = 1.f, sa = 0.f;
        if (p0 + p < npts) {
            const float* cp = coords + (size_t)(p0 + p) * 6 + v * 3;
            float X = cp[0], Yc = cp[1], Z = cp[2];
            float r = sqrtf(X * X + Yc * Yc + Z * Z);
            ct = Z / r;
            ct = fminf(1.f, fmaxf(-1.f, ct));
            st = sqrtf(fmaxf(0.f, 1.f - ct * ct));     // sin(arccos(ct)) >= 0
            float rxy2 = X * X + Yc * Yc;
            if (rxy2 > 0.f) {                          // atan2(0,0)=0
                float irxy = rsqrtf(rxy2);
                ca = X * irxy; sa = Yc * irxy;
            }
        }
        float* pvd = s_pv + t * PV_STRIDE;
        pvd[0] = ct;
        float cm = 1.f, sv = 0.f, pm = 1.f;
        pvd[1] = cm; pvd[22] = sv; pvd[43] = pm;
        #pragma unroll
        for (int m = 1; m <= LMAX; ++m) {
            float cn = cm * ca - sv * sa;              // cos(m*azim)
            sv = cm * sa + sv * ca;                    // sin(m*azim)
            cm = cn;
            pm *= (1.f - 2.f * (float)m) * st;         // Condon-Shortley diag
            pvd[1 + m] = cm; pvd[22 + m] = sv; pvd[43 + m] = pm;
        }
    }
    __syncthreads();

    // Phase 1: lane = pv; warp-uniform m columns (critical path 21 rows).
    if (p0 + (lane >> 1) < npts) {
        const float* pvd = s_pv + lane * PV_STRIDE;
        const float  ct  = pvd[0];
        float* ps = s_psi + lane * KVAL;

        int mvals[2];
        mvals[0] = warp;                                     // m = 0..15
        mvals[1] = (warp >= 7 && warp <= 11) ? 27 - warp : -1;  // m = 20..16
        const int nmv = (mvals[1] >= 0) ? 2 : 1;

        for (int k = 0; k < nmv; ++k) {
            const int m = mvals[k];
            float cm = pvd[1 + m], sv = pvd[22 + m], pm = pvd[43 + m];
            float q2 = c_tab.seed[m] * pm;             // l = m
            int base = m * (m + 1);
            if (m) ps[base - m] = q2 * sv;             // warp-uniform branch
            ps[base + m] = q2 * cm;
            if (m < LMAX) {
                float q1 = c_tab.c1[m] * ct * q2;      // l = m+1
                base = (m + 1) * (m + 2);
                if (m) ps[base - m] = q1 * sv;
                ps[base + m] = q1 * cm;
                int idx = (m + 2) * NM + m;
                for (int l = m + 2; l <= LMAX; ++l, idx += NM) {
                    F2 ab = c_tab.AB[idx];             // uniform constant load
                    float qn = ab.x * ct * q1 - ab.y * q2;
                    q2 = q1; q1 = qn;
                    base += 2 * l;                     // = l*(l+1)
                    if (m) ps[base - m] = qn * sv;
                    ps[base + m] = qn * cm;
                }
            }
        }
    }
    __syncthreads();

    // Phase 2: rolled loop, two points per thread, coalesced stores.
    for (int p = (t >> 8); p < BPTS; p += 2) {
        int gp = p0 + p;
        if (gp < npts) {
            float a = s_psi[(2 * p)     * KVAL + pi];
            float b = s_psi[(2 * p + 1) * KVAL + pj];
            out[(size_t)gp * RANK_ + rk] = a * b;
        }
    }
}

extern "C" void kernel_launch(void* const* d_in, const int* in_sizes, int n_in,
                              void* d_out, int out_size) {
    const float* coords = (const float*)d_in[0];
    const int*   ri     = (const int*)d_in[1];
    const int*   rj     = (const int*)d_in[2];
    float*       out    = (float*)d_out;
    int npts = in_sizes[0] / 6;

    const size_t SMEM = (size_t)(NPV * KVAL            // psi
                                 + NPV * PV_STRIDE)    // chains
                        * sizeof(float);
    cudaFuncSetAttribute((const void*)sh_kernel,
                         cudaFuncAttributeMaxDynamicSharedMemorySize, (int)SMEM);

    int grid = (npts + BPTS - 1) / BPTS;
    sh_kernel<<<grid, NTHREADS, SMEM>>>(coords, ri, rj, out, npts);
}

// round 11
// speedup vs baseline: 3.6130x; 1.4351x over previous
#include <cuda_runtime.h>
#include <math.h>

#define LMAX 20
#define NM   21           // number of m columns (0..20)
#define KVAL 441          // (LMAX+1)^2
#define RANK_ 256
#define BPTS 16           // points per CTA
#define NPV  (BPTS * 2)   // 32 (point,vector) pairs
#define NTHREADS 512      // 16 warps: one m-column per warp (+5 short cols)
#define PV_STRIDE 65      // padded (coprime with 32 banks)

// --------------------------------------------------------------------------
// Compile-time tables (same product-form normd() math as all passing rounds,
// constexpr double + Newton sqrt). Used ONLY in constant expressions below,
// so A/B/seed/c1 become float IMMEDIATES in SASS (no LDC, rt=1 FFMA-imm).
//   Q(m,m)   = seed[m] * pmm
//   Q(m+1,m) = c1[m] * ct * Q(m,m)
//   Q(l,m)   = A(l,m) * ct * Q(l-1,m) - B(l,m) * Q(l-2,m)
// --------------------------------------------------------------------------
struct F2 { float x, y; };
struct Tab {
    F2    AB[NM * NM];
    float seed[NM];
    float c1[NM];
};

constexpr double csqrt(double v) {
    double g = v > 1.0 ? v : 1.0;
    for (int i = 0; i < 100; ++i) g = 0.5 * (g + v / g);
    return g;
}

constexpr double cnormd(int l, int m) {
    // sqrt( (2l+1)/(4pi) * (l-m)!/(l+m)! ) -- product then one divide
    double p = 1.0;
    for (int k = l - m + 1; k <= l + m; ++k) p *= (double)k;  // (l+m)!/(l-m)!
    return csqrt((2.0 * l + 1.0) / (4.0 * 3.14159265358979323846) / p);
}

constexpr Tab make_tab() {
    Tab t{};
    for (int m = 0; m <= LMAX; ++m) {
        double s = cnormd(m, m);
        if (m > 0) s *= 1.4142135623730951;   // sqrt(2) for m != 0 terms
        t.seed[m] = (float)s;
        t.c1[m] = (m < LMAX)
            ? (float)((2.0 * m + 1.0) * cnormd(m + 1, m) / cnormd(m, m))
            : 0.f;
    }
    for (int l = 0; l <= LMAX; ++l)
        for (int m = 0; m <= LMAX; ++m) {
            F2 ab{0.f, 0.f};
            if (l >= m + 2) {
                ab.x = (float)((2.0 * l - 1.0) / (double)(l - m)
                               * cnormd(l, m) / cnormd(l - 1, m));
                ab.y = (float)((double)(l + m - 1) / (double)(l - m)
                               * cnormd(l, m) / cnormd(l - 2, m));
            }
            t.AB[l * NM + m] = ab;
        }
    return t;
}

constexpr Tab k_tab = make_tab();

// Fully-unrolled recurrence rows for column M, l = L..LMAX.
// All coefficients are immediates; all store offsets are immediates.
template<int M, int L>
__device__ __forceinline__ void rows(float ct, float cm, float sv,
                                     float q1, float q2, float* ps) {
    if constexpr (L <= LMAX) {
        constexpr float A = k_tab.AB[L * NM + M].x;
        constexpr float B = k_tab.AB[L * NM + M].y;
        float qn = A * ct * q1 - B * q2;
        ps[L * (L + 1) + M] = qn * cm;
        if constexpr (M > 0) ps[L * (L + 1) - M] = qn * sv;
        rows<M, L + 1>(ct, cm, sv, qn, q1, ps);
    }
}

template<int M>
__device__ __forceinline__ void do_col(const float* pvd, float* ps, float ct) {
    float cm = pvd[1 + M], sv = pvd[22 + M], pm = pvd[43 + M];
    constexpr float S = k_tab.seed[M];
    float q2 = S * pm;                                  // l = M
    ps[M * (M + 1) + M] = q2 * cm;
    if constexpr (M > 0) ps[M * (M + 1) - M] = q2 * sv;
    if constexpr (M < LMAX) {
        constexpr float C = k_tab.c1[M];
        float q1 = C * ct * q2;                         // l = M+1
        ps[(M + 1) * (M + 2) + M] = q1 * cm;
        if constexpr (M > 0) ps[(M + 1) * (M + 2) - M] = q1 * sv;
        rows<M, M + 2>(ct, cm, sv, q1, q2, ps);
    }
}

// --------------------------------------------------------------------------
// Main kernel: one CTA = BPTS points = 32 (point,vector) pairs, 16 warps.
// Phase 0: warp 0, lane = pv: ct + trig/diagonal chains into s_pv.
// Phase 1: lane = pv; warp w -> column m=w (templated, fully unrolled),
//          warps 7..11 also take m = 27-w. Critical path 21 rows.
// Phase 2: thread t owns rank (t & 255); rolled loop (round-8 lesson:
//          do NOT batch-unroll the gathers).
// --------------------------------------------------------------------------
__global__ __launch_bounds__(NTHREADS, 1) void sh_kernel(
    const float* __restrict__ coords, const int* __restrict__ ri,
    const int* __restrict__ rj, float* __restrict__ out, int npts)
{
    extern __shared__ float smem[];
    float* s_psi = smem;                    // NPV*KVAL
    float* s_pv  = s_psi + NPV * KVAL;      // NPV*PV_STRIDE

    const int t    = threadIdx.x;
    const int warp = t >> 5;
    const int lane = t & 31;
    const int p0   = blockIdx.x * BPTS;

    // Per-thread rank data for phase 2 (identity mapping, coalesced LDG).
    const int rk = t & (RANK_ - 1);
    const int pi = ri[rk];
    const int pj = rj[rk];

    // Phase 0: per (point, vector) trig / diagonal chains (32 threads).
    if (t < NPV) {
        int p = t >> 1, v = t & 1;
        float ct = 0.f, st = 0.f, ca = 1.f, sa = 0.f;
        if (p0 + p < npts) {
            const float* cp = coords + (size_t)(p0 + p) * 6 + v * 3;
            float X = cp[0], Yc = cp[1], Z = cp[2];
            float r = sqrtf(X * X + Yc * Yc + Z * Z);
            ct = Z / r;
            ct = fminf(1.f, fmaxf(-1.f, ct));
            st = sqrtf(fmaxf(0.f, 1.f - ct * ct));     // sin(arccos(ct)) >= 0
            float rxy2 = X * X + Yc * Yc;
            if (rxy2 > 0.f) {                          // atan2(0,0)=0
                float irxy = rsqrtf(rxy2);
                ca = X * irxy; sa = Yc * irxy;
            }
        }
        float* pvd = s_pv + t * PV_STRIDE;
        pvd[0] = ct;
        float cm = 1.f, sv = 0.f, pm = 1.f;
        pvd[1] = cm; pvd[22] = sv; pvd[43] = pm;
        #pragma unroll
        for (int m = 1; m <= LMAX; ++m) {
            float cn = cm * ca - sv * sa;              // cos(m*azim)
            sv = cm * sa + sv * ca;                    // sin(m*azim)
            cm = cn;
            pm *= (1.f - 2.f * (float)m) * st;         // Condon-Shortley diag
            pvd[1 + m] = cm; pvd[22 + m] = sv; pvd[43 + m] = pm;
        }
    }
    __syncthreads();

    // Phase 1: lane = pv; warp-uniform templated columns.
    if (p0 + (lane >> 1) < npts) {
        const float* pvd = s_pv + lane * PV_STRIDE;
        const float  ct  = pvd[0];
        float* ps = s_psi + lane * KVAL;

        switch (warp) {
            case 0:  do_col<0 >(pvd, ps, ct); break;
            case 1:  do_col<1 >(pvd, ps, ct); break;
            case 2:  do_col<2 >(pvd, ps, ct); break;
            case 3:  do_col<3 >(pvd, ps, ct); break;
            case 4:  do_col<4 >(pvd, ps, ct); break;
            case 5:  do_col<5 >(pvd, ps, ct); break;
            case 6:  do_col<6 >(pvd, ps, ct); break;
            case 7:  do_col<7 >(pvd, ps, ct); do_col<20>(pvd, ps, ct); break;
            case 8:  do_col<8 >(pvd, ps, ct); do_col<19>(pvd, ps, ct); break;
            case 9:  do_col<9 >(pvd, ps, ct); do_col<18>(pvd, ps, ct); break;
            case 10: do_col<10>(pvd, ps, ct); do_col<17>(pvd, ps, ct); break;
            case 11: do_col<11>(pvd, ps, ct); do_col<16>(pvd, ps, ct); break;
            case 12: do_col<12>(pvd, ps, ct); break;
            case 13: do_col<13>(pvd, ps, ct); break;
            case 14: do_col<14>(pvd, ps, ct); break;
            case 15: do_col<15>(pvd, ps, ct); break;
        }
    }
    __syncthreads();

    // Phase 2: rolled loop, two points per thread, coalesced stores.
    for (int p = (t >> 8); p < BPTS; p += 2) {
        int gp = p0 + p;
        if (gp < npts) {
            float a = s_psi[(2 * p)     * KVAL + pi];
            float b = s_psi[(2 * p + 1) * KVAL + pj];
            out[(size_t)gp * RANK_ + rk] = a * b;
        }
    }
}

extern "C" void kernel_launch(void* const* d_in, const int* in_sizes, int n_in,
                              void* d_out, int out_size) {
    const float* coords = (const float*)d_in[0];
    const int*   ri     = (const int*)d_in[1];
    const int*   rj     = (const int*)d_in[2];
    float*       out    = (float*)d_out;
    int npts = in_sizes[0] / 6;

    const size_t SMEM = (size_t)(NPV * KVAL            // psi
                                 + NPV * PV_STRIDE)    // chains
                        * sizeof(float);
    cudaFuncSetAttribute((const void*)sh_kernel,
                         cudaFuncAttributeMaxDynamicSharedMemorySize, (int)SMEM);

    int grid = (npts + BPTS - 1) / BPTS;
    sh_kernel<<<grid, NTHREADS, SMEM>>>(coords, ri, rj, out, npts);
}